// round 14
// baseline (speedup 1.0000x reference)
#include <cuda_runtime.h>
#include <cuda_fp16.h>
#include <math.h>
#include <stdint.h>

#define SEQ     2048
#define DIM     4096
#define NH      32
#define NKV     8
#define HD      128
#define WINDOW  1024
#define QDIM    (NH * HD)            // 4096
#define KVDIM   (NKV * HD)           // 1024
#define QKVDIM  (QDIM + 2 * KVDIM)   // 6144
#define ATT_SCALE 0.08838834764831845f

// ---------------------------------------------------------------------------
// Scratch
// ---------------------------------------------------------------------------
__device__ __align__(256) __half g_xs   [SEQ * DIM];
__device__ __align__(256) __half g_os   [SEQ * QDIM];
__device__ __align__(256) __half g_wqkvs[QKVDIM * DIM];
__device__ __align__(256) __half g_wos  [DIM * QDIM];

__device__ __align__(256) __half g_qh[SEQ * QDIM], g_ql[SEQ * QDIM];
__device__ __align__(256) __half g_kh[SEQ * KVDIM];
__device__ __align__(256) __half g_vh[SEQ * KVDIM];

// ---------------------------------------------------------------------------
// helpers
// ---------------------------------------------------------------------------
__device__ __forceinline__ uint32_t smem_u32(const void* p) {
    return (uint32_t)__cvta_generic_to_shared(p);
}
__device__ __forceinline__ void cp_async16(uint32_t dst, const void* src) {
    asm volatile("cp.async.cg.shared.global [%0], [%1], 16;\n" :: "r"(dst), "l"(src));
}
__device__ __forceinline__ void mma16816(float* c, const uint32_t* a, const uint32_t* b) {
    asm volatile(
        "mma.sync.aligned.m16n8k16.row.col.f32.f16.f16.f32 "
        "{%0,%1,%2,%3}, {%4,%5,%6,%7}, {%8,%9}, {%0,%1,%2,%3};\n"
        : "+f"(c[0]), "+f"(c[1]), "+f"(c[2]), "+f"(c[3])
        : "r"(a[0]), "r"(a[1]), "r"(a[2]), "r"(a[3]), "r"(b[0]), "r"(b[1]));
}
__device__ __forceinline__ void ldsm4(uint32_t* r, uint32_t addr) {
    asm volatile("ldmatrix.sync.aligned.m8n8.x4.shared.b16 {%0,%1,%2,%3}, [%4];\n"
        : "=r"(r[0]), "=r"(r[1]), "=r"(r[2]), "=r"(r[3]) : "r"(addr));
}
__device__ __forceinline__ void ldsm4t(uint32_t* r, uint32_t addr) {
    asm volatile("ldmatrix.sync.aligned.m8n8.x4.trans.shared.b16 {%0,%1,%2,%3}, [%4];\n"
        : "=r"(r[0]), "=r"(r[1]), "=r"(r[2]), "=r"(r[3]) : "r"(addr));
}
__device__ __forceinline__ uint32_t pack2h(float p0, float p1) {
    __half h0 = __float2half_rn(p0), h1 = __float2half_rn(p1);
    return ((uint32_t)*(uint16_t*)&h1 << 16) | (uint32_t)*(uint16_t*)&h0;
}
__device__ __forceinline__ void split_pack(float p0, float p1, uint32_t& hi, uint32_t& lo) {
    __half h0 = __float2half_rn(p0), h1 = __float2half_rn(p1);
    hi = ((uint32_t)*(uint16_t*)&h1 << 16) | (uint32_t)*(uint16_t*)&h0;
    __half l0 = __float2half_rn(p0 - __half2float(h0));
    __half l1 = __float2half_rn(p1 - __half2float(h1));
    lo = ((uint32_t)*(uint16_t*)&l1 << 16) | (uint32_t)*(uint16_t*)&l0;
}

// ---------------------------------------------------------------------------
// Merged fp32 -> fp16 conversion: one kernel, 16 elems/thread (R12 version)
// ---------------------------------------------------------------------------
#define U_X    ((SEQ * DIM) / 16)
#define U_WQ   ((QDIM * DIM) / 16)
#define U_WK   ((KVDIM * DIM) / 16)
#define U_WQKV (U_WQ + 2 * U_WK)
#define U_WO   ((DIM * QDIM) / 16)
#define U_TOT  (U_X + U_WQKV + U_WO)

__global__ void cvt_all(const float* __restrict__ x,
                        const float* __restrict__ wq,
                        const float* __restrict__ wk,
                        const float* __restrict__ wv,
                        const float* __restrict__ wo,
                        __half* __restrict__ xs,
                        __half* __restrict__ wqkvs,
                        __half* __restrict__ wos)
{
    size_t u = (size_t)blockIdx.x * blockDim.x + threadIdx.x;
    if (u >= U_TOT) return;
    const float* s;
    __half* d;
    if (u < U_X) {
        s = x + u * 16; d = xs + u * 16;
    } else if (u < U_X + U_WQKV) {
        size_t v = u - U_X;
        d = wqkvs + v * 16;
        if (v < U_WQ)             s = wq + v * 16;
        else if (v < U_WQ + U_WK) s = wk + (v - U_WQ) * 16;
        else                      s = wv + (v - U_WQ - U_WK) * 16;
    } else {
        size_t v = u - U_X - U_WQKV;
        s = wo + v * 16; d = wos + v * 16;
    }
    float4 a0 = *(const float4*)(s);
    float4 a1 = *(const float4*)(s + 4);
    float4 a2 = *(const float4*)(s + 8);
    float4 a3 = *(const float4*)(s + 12);
    uint4 o0, o1;
    o0.x = pack2h(a0.x, a0.y); o0.y = pack2h(a0.z, a0.w);
    o0.z = pack2h(a1.x, a1.y); o0.w = pack2h(a1.z, a1.w);
    o1.x = pack2h(a2.x, a2.y); o1.y = pack2h(a2.z, a2.w);
    o1.z = pack2h(a3.x, a3.y); o1.w = pack2h(a3.z, a3.w);
    *(uint4*)(d)     = o0;
    *(uint4*)(d + 8) = o1;
}

// ---------------------------------------------------------------------------
// fp16 NT GEMM: 128x128 block tile, BK=64, 3-stage cp.async ring.
// 8 warps (2Mx4N), warp tile 64x32, 2 CTAs/SM.
// ks order staggered per warp (ks = (ksi + w) & 3) to de-phase the
// ldsm/crossbar burst from the mma burst across warps.
// EPI=0: plain fp32 C. EPI=1: fused rope/scale/split epilogue.
// ---------------------------------------------------------------------------
#define BM 128
#define BN 128
#define BK 64
#define KP 72
#define NST 3
#define STG_H ((BM + BN) * KP)
#define GEMM_SMEM (NST * STG_H * 2)      // 110592 bytes

template <int EPI>
__global__ __launch_bounds__(256, 2) void gemm_fp16_nt(
    const __half* __restrict__ A, const __half* __restrict__ B,
    float* __restrict__ C,
    __half* __restrict__ Qh, __half* __restrict__ Ql,
    __half* __restrict__ Kh, __half* __restrict__ Vh,
    const float* __restrict__ cosb, const float* __restrict__ sinb,
    int M, int N, int K)
{
    extern __shared__ __half smg[];

    const int tid  = threadIdx.x;
    const int lane = tid & 31;
    const int w    = tid >> 5;
    const int bm   = blockIdx.y * BM;
    const int bn   = blockIdx.x * BN;
    const int warp_m = (w & 1) * 64;
    const int warp_n = (w >> 1) * 32;

    float acc[4][4][4];
#pragma unroll
    for (int i = 0; i < 4; i++)
#pragma unroll
        for (int j = 0; j < 4; j++)
#pragma unroll
            for (int r = 0; r < 4; r++) acc[i][j][r] = 0.0f;

    const int KB = K / BK;

    auto load_stage = [&](int kb) {
        __half* As = smg + (kb % NST) * STG_H;
        __half* Bs = As + BM * KP;
        int k0 = kb * BK;
#pragma unroll
        for (int i = 0; i < 4; i++) {
            int id  = tid + i * 256;
            int row = id >> 3;
            int c8  = (id & 7) * 8;
            cp_async16(smem_u32(As + row * KP + c8),
                       A + (size_t)(bm + row) * K + k0 + c8);
        }
#pragma unroll
        for (int i = 0; i < 4; i++) {
            int id  = tid + i * 256;
            int row = id >> 3;
            int c8  = (id & 7) * 8;
            cp_async16(smem_u32(Bs + row * KP + c8),
                       B + (size_t)(bn + row) * K + k0 + c8);
        }
        asm volatile("cp.async.commit_group;\n");
    };

    load_stage(0);
    load_stage(1);

    for (int kb = 0; kb < KB; kb++) {
        asm volatile("cp.async.wait_group 1;\n");
        __syncthreads();
        if (kb + 2 < KB) {
            load_stage(kb + 2);
        } else {
            asm volatile("cp.async.commit_group;\n");
        }

        __half* As = smg + (kb % NST) * STG_H;
        __half* Bs = As + BM * KP;

#pragma unroll
        for (int ksi = 0; ksi < 4; ksi++) {
            const int ks = (ksi + w) & 3;   // per-warp phase stagger
            uint32_t a_frag[4][4];
#pragma unroll
            for (int mt = 0; mt < 4; mt++) {
                uint32_t addr = smem_u32(
                    As + (warp_m + mt * 16 + (lane & 15)) * KP
                       + ks * 16 + (lane >> 4) * 8);
                ldsm4(a_frag[mt], addr);
            }
            uint32_t b_frag[4][2];
#pragma unroll
            for (int half = 0; half < 2; half++) {
                int nt0 = half * 2;
                int row = warp_n + nt0 * 8 + ((lane >> 4) & 1) * 8 + (lane & 7);
                int col = ks * 16 + ((lane >> 3) & 1) * 8;
                uint32_t r4[4];
                ldsm4(r4, smem_u32(Bs + row * KP + col));
                b_frag[nt0][0] = r4[0]; b_frag[nt0][1] = r4[1];
                b_frag[nt0 + 1][0] = r4[2]; b_frag[nt0 + 1][1] = r4[3];
            }
#pragma unroll
            for (int mt = 0; mt < 4; mt++)
#pragma unroll
                for (int nt = 0; nt < 4; nt++)
                    mma16816(acc[mt][nt], a_frag[mt], b_frag[nt]);
        }
    }

    const int g   = lane >> 2;
    const int tig = lane & 3;

    if (EPI == 0) {
#pragma unroll
        for (int mt = 0; mt < 4; mt++) {
#pragma unroll
            for (int nt = 0; nt < 4; nt++) {
                float* c0 = C + (size_t)(bm + warp_m + mt * 16 + g) * N
                              + bn + warp_n + nt * 8 + tig * 2;
                float* c1 = c0 + 8 * (size_t)N;
                *(float2*)c0 = make_float2(acc[mt][nt][0], acc[mt][nt][1]);
                *(float2*)c1 = make_float2(acc[mt][nt][2], acc[mt][nt][3]);
            }
        }
    } else {
        const int region = (bn < QDIM) ? 0 : ((bn < QDIM + KVDIM) ? 1 : 2);
#pragma unroll
        for (int mt = 0; mt < 4; mt++) {
            int row0 = bm + warp_m + mt * 16 + g;
            int row1 = row0 + 8;
#pragma unroll
            for (int nt = 0; nt < 4; nt++) {
                int n0 = bn + warp_n + nt * 8 + tig * 2;
                float a00 = acc[mt][nt][0], a01 = acc[mt][nt][1];
                float a10 = acc[mt][nt][2], a11 = acc[mt][nt][3];
                if (region == 2) {
                    int col = n0 - (QDIM + KVDIM);
                    *(uint32_t*)(Vh + (size_t)row0 * KVDIM + col) = pack2h(a00, a01);
                    *(uint32_t*)(Vh + (size_t)row1 * KVDIM + col) = pack2h(a10, a11);
                } else {
                    int col = (region == 0) ? n0 : (n0 - QDIM);
                    int p = (col & (HD - 1)) >> 1;
                    float c0 = cosb[row0 * (HD / 2) + p], s0 = sinb[row0 * (HD / 2) + p];
                    float c1 = cosb[row1 * (HD / 2) + p], s1 = sinb[row1 * (HD / 2) + p];
                    float r00 = a00 * c0 - a01 * s0, r01 = a00 * s0 + a01 * c0;
                    float r10 = a10 * c1 - a11 * s1, r11 = a10 * s1 + a11 * c1;
                    if (region == 0) {
                        r00 *= ATT_SCALE; r01 *= ATT_SCALE;
                        r10 *= ATT_SCALE; r11 *= ATT_SCALE;
                        uint32_t hi, lo;
                        split_pack(r00, r01, hi, lo);
                        *(uint32_t*)(Qh + (size_t)row0 * QDIM + col) = hi;
                        *(uint32_t*)(Ql + (size_t)row0 * QDIM + col) = lo;
                        split_pack(r10, r11, hi, lo);
                        *(uint32_t*)(Qh + (size_t)row1 * QDIM + col) = hi;
                        *(uint32_t*)(Ql + (size_t)row1 * QDIM + col) = lo;
                    } else {
                        *(uint32_t*)(Kh + (size_t)row0 * KVDIM + col) = pack2h(r00, r01);
                        *(uint32_t*)(Kh + (size_t)row1 * KVDIM + col) = pack2h(r10, r11);
                    }
                }
            }
        }
    }
}

// ---------------------------------------------------------------------------
// Flash attention, fp16: S = (Qh+Ql)*Kh^T (B fragments loaded once),
// O += Ph*Vh. Writes plain fp16 output. (R12 version, natural ordering.)
// ---------------------------------------------------------------------------
#define PDD 136
#define ATT_SMEM ((2 * 128 * PDD + 2 * 2 * 64 * PDD) * 2)

__global__ __launch_bounds__(256, 1) void attn_mma_kernel(
    const __half* __restrict__ Qh, const __half* __restrict__ Ql,
    const __half* __restrict__ Kh, const __half* __restrict__ Vh,
    __half* __restrict__ OS)
{
    extern __shared__ __half sm[];
    __half* sQh = sm;
    __half* sQl = sQh + 128 * PDD;
    __half* sKV = sQl + 128 * PDD;

    const int tid  = threadIdx.x;
    const int lane = tid & 31;
    const int w    = tid >> 5;
    const int q0   = blockIdx.x * 64;
    const int kvh  = blockIdx.y >> 1;
    const int h0   = kvh * 4 + (blockIdx.y & 1) * 2;

    const int warp_row = w * 16;
    const int s_row0 = q0 + (warp_row & 63) + (lane >> 2);
    const int s_row1 = s_row0 + 8;
    const int h_out  = h0 + (warp_row >> 6);

#pragma unroll
    for (int i = 0; i < 8; i++) {
        int id = tid + i * 256;
        int r = id >> 4, c8 = (id & 15) * 8;
        int s = q0 + (r & 63), h = h0 + (r >> 6);
        size_t g = ((size_t)s * NH + h) * HD + c8;
        cp_async16(smem_u32(sQh + r * PDD + c8), Qh + g);
        cp_async16(smem_u32(sQl + r * PDD + c8), Ql + g);
    }
    asm volatile("cp.async.commit_group;\n");

    float m0 = -1e30f, m1 = -1e30f, l0 = 0.f, l1 = 0.f;
    float o_acc[16][4];
#pragma unroll
    for (int i = 0; i < 16; i++)
#pragma unroll
        for (int r = 0; r < 4; r++) o_acc[i][r] = 0.f;

    int jlo = q0 - (WINDOW - 1); if (jlo < 0) jlo = 0;
    const int t0 = jlo >> 6, t1 = (q0 + 63) >> 6;

    auto load_kv = [&](int kt, int buf) {
        __half* b = sKV + buf * 2 * 64 * PDD;
        int kt0 = kt << 6;
#pragma unroll
        for (int i = 0; i < 4; i++) {
            int id = tid + i * 256;
            int r = id >> 4, c8 = (id & 15) * 8;
            size_t g = ((size_t)(kt0 + r) * NKV + kvh) * HD + c8;
            cp_async16(smem_u32(b + r * PDD + c8), Kh + g);
            cp_async16(smem_u32(b + 64 * PDD + r * PDD + c8), Vh + g);
        }
        asm volatile("cp.async.commit_group;\n");
    };

    load_kv(t0, 0);

    for (int kt = t0; kt <= t1; kt++) {
        const int buf = (kt - t0) & 1;
        const int kt0 = kt << 6;
        if (kt + 1 <= t1) {
            load_kv(kt + 1, buf ^ 1);
            asm volatile("cp.async.wait_group 1;\n");
        } else {
            asm volatile("cp.async.wait_group 0;\n");
        }
        __syncthreads();

        __half* bKh = sKV + buf * 2 * 64 * PDD;
        __half* bVh = bKh + 64 * PDD;

        float S[8][4];
#pragma unroll
        for (int nt = 0; nt < 8; nt++)
#pragma unroll
            for (int r = 0; r < 4; r++) S[nt][r] = 0.f;

#pragma unroll
        for (int ks = 0; ks < 8; ks++) {
            uint32_t a_hi[4], a_lo[4];
            uint32_t a_off = (warp_row + (lane & 15)) * PDD
                           + ks * 16 + (lane >> 4) * 8;
            ldsm4(a_hi, smem_u32(sQh + a_off));
            ldsm4(a_lo, smem_u32(sQl + a_off));
#pragma unroll
            for (int n2 = 0; n2 < 4; n2++) {
                int row = n2 * 16 + ((lane >> 4) & 1) * 8 + (lane & 7);
                int col = ks * 16 + ((lane >> 3) & 1) * 8;
                uint32_t b4[4];
                ldsm4(b4, smem_u32(bKh + row * PDD + col));
                mma16816(S[n2 * 2],     a_hi, b4);
                mma16816(S[n2 * 2 + 1], a_hi, b4 + 2);
                mma16816(S[n2 * 2],     a_lo, b4);
                mma16816(S[n2 * 2 + 1], a_lo, b4 + 2);
            }
        }

        bool edge = (kt0 + 63 > q0) || (kt0 < q0 + 63 - (WINDOW - 1));
        if (edge) {
#pragma unroll
            for (int nt = 0; nt < 8; nt++) {
                int jc = kt0 + nt * 8 + (lane & 3) * 2;
#pragma unroll
                for (int e = 0; e < 4; e++) {
                    int j = jc + (e & 1);
                    int s = (e < 2) ? s_row0 : s_row1;
                    if (!((j <= s) && (s - j < WINDOW))) S[nt][e] = -1e30f;
                }
            }
        }

        float mx0 = -1e30f, mx1 = -1e30f;
#pragma unroll
        for (int nt = 0; nt < 8; nt++) {
            mx0 = fmaxf(mx0, fmaxf(S[nt][0], S[nt][1]));
            mx1 = fmaxf(mx1, fmaxf(S[nt][2], S[nt][3]));
        }
#pragma unroll
        for (int off = 1; off <= 2; off <<= 1) {
            mx0 = fmaxf(mx0, __shfl_xor_sync(0xffffffffu, mx0, off));
            mx1 = fmaxf(mx1, __shfl_xor_sync(0xffffffffu, mx1, off));
        }
        float mn0 = fmaxf(m0, mx0), mn1 = fmaxf(m1, mx1);
        float al0 = __expf(m0 - mn0), al1 = __expf(m1 - mn1);
        m0 = mn0; m1 = mn1;

        float sum0 = 0.f, sum1 = 0.f;
        uint32_t phi[4][4];
#pragma unroll
        for (int j2 = 0; j2 < 4; j2++) {
            float p00 = __expf(S[2 * j2][0] - mn0);
            float p01 = __expf(S[2 * j2][1] - mn0);
            float p02 = __expf(S[2 * j2][2] - mn1);
            float p03 = __expf(S[2 * j2][3] - mn1);
            float p10 = __expf(S[2 * j2 + 1][0] - mn0);
            float p11 = __expf(S[2 * j2 + 1][1] - mn0);
            float p12 = __expf(S[2 * j2 + 1][2] - mn1);
            float p13 = __expf(S[2 * j2 + 1][3] - mn1);
            sum0 += p00 + p01 + p10 + p11;
            sum1 += p02 + p03 + p12 + p13;
            phi[j2][0] = pack2h(p00, p01);
            phi[j2][1] = pack2h(p02, p03);
            phi[j2][2] = pack2h(p10, p11);
            phi[j2][3] = pack2h(p12, p13);
        }
#pragma unroll
        for (int off = 1; off <= 2; off <<= 1) {
            sum0 += __shfl_xor_sync(0xffffffffu, sum0, off);
            sum1 += __shfl_xor_sync(0xffffffffu, sum1, off);
        }
        l0 = l0 * al0 + sum0;
        l1 = l1 * al1 + sum1;

#pragma unroll
        for (int i = 0; i < 16; i++) {
            o_acc[i][0] *= al0; o_acc[i][1] *= al0;
            o_acc[i][2] *= al1; o_acc[i][3] *= al1;
        }

#pragma unroll
        for (int j2 = 0; j2 < 4; j2++) {
            int row = j2 * 16 + ((lane >> 3) & 1) * 8 + (lane & 7);
#pragma unroll
            for (int d2 = 0; d2 < 8; d2++) {
                int col = d2 * 16 + ((lane >> 4) & 1) * 8;
                uint32_t bh[4];
                ldsm4t(bh, smem_u32(bVh + row * PDD + col));
                mma16816(o_acc[d2 * 2],     phi[j2], bh);
                mma16816(o_acc[d2 * 2 + 1], phi[j2], bh + 2);
            }
        }
        __syncthreads();
    }

    float inv0 = 1.0f / l0, inv1 = 1.0f / l1;
#pragma unroll
    for (int d2 = 0; d2 < 16; d2++) {
        int d = d2 * 8 + (lane & 3) * 2;
        *(uint32_t*)(OS + (size_t)s_row0 * QDIM + h_out * HD + d) =
            pack2h(o_acc[d2][0] * inv0, o_acc[d2][1] * inv0);
        *(uint32_t*)(OS + (size_t)s_row1 * QDIM + h_out * HD + d) =
            pack2h(o_acc[d2][2] * inv1, o_acc[d2][3] * inv1);
    }
}

// ---------------------------------------------------------------------------
// Launch
// ---------------------------------------------------------------------------
extern "C" void kernel_launch(void* const* d_in, const int* in_sizes, int n_in,
                              void* d_out, int out_size)
{
    const float* x    = (const float*)d_in[0];
    const float* wq   = (const float*)d_in[1];
    const float* wk   = (const float*)d_in[2];
    const float* wv   = (const float*)d_in[3];
    const float* wo   = (const float*)d_in[4];
    const float* cosb = (const float*)d_in[5];
    const float* sinb = (const float*)d_in[6];
    float* out = (float*)d_out;

    __half *xs, *os, *wqkvs, *wos, *qh, *ql, *kh, *vh;
    cudaGetSymbolAddress((void**)&xs, g_xs);
    cudaGetSymbolAddress((void**)&os, g_os);
    cudaGetSymbolAddress((void**)&wqkvs, g_wqkvs);
    cudaGetSymbolAddress((void**)&wos, g_wos);
    cudaGetSymbolAddress((void**)&qh, g_qh);
    cudaGetSymbolAddress((void**)&ql, g_ql);
    cudaGetSymbolAddress((void**)&kh, g_kh);
    cudaGetSymbolAddress((void**)&vh, g_vh);

    cudaFuncSetAttribute(gemm_fp16_nt<0>,
                         cudaFuncAttributeMaxDynamicSharedMemorySize, GEMM_SMEM);
    cudaFuncSetAttribute(gemm_fp16_nt<1>,
                         cudaFuncAttributeMaxDynamicSharedMemorySize, GEMM_SMEM);
    cudaFuncSetAttribute(attn_mma_kernel,
                         cudaFuncAttributeMaxDynamicSharedMemorySize, ATT_SMEM);

    // single merged conversion launch
    cvt_all<<<(U_TOT + 255) / 256, 256>>>(x, wq, wk, wv, wo, xs, wqkvs, wos);

    // fused QKV projection + rope + scale + split epilogue
    {
        dim3 g(QKVDIM / BN, SEQ / BM);
        gemm_fp16_nt<1><<<g, 256, GEMM_SMEM>>>(
            xs, wqkvs, nullptr, qh, ql, kh, vh, cosb, sinb, SEQ, QKVDIM, DIM);
    }

    // flash attention
    {
        dim3 ga(SEQ / 64, NKV * 2);
        attn_mma_kernel<<<ga, 256, ATT_SMEM>>>(qh, ql, kh, vh, os);
    }

    // output projection
    {
        dim3 g(DIM / BN, SEQ / BM);
        gemm_fp16_nt<0><<<g, 256, GEMM_SMEM>>>(
            os, wos, out, nullptr, nullptr, nullptr, nullptr, nullptr, nullptr,
            SEQ, DIM, QDIM);
    }
}

// round 15
// speedup vs baseline: 1.0243x; 1.0243x over previous
#include <cuda_runtime.h>
#include <cuda_fp16.h>
#include <math.h>
#include <stdint.h>

#define SEQ     2048
#define DIM     4096
#define NH      32
#define NKV     8
#define HD      128
#define WINDOW  1024
#define QDIM    (NH * HD)            // 4096
#define KVDIM   (NKV * HD)           // 1024
#define QKVDIM  (QDIM + 2 * KVDIM)   // 6144
#define ATT_SCALE 0.08838834764831845f

// ---------------------------------------------------------------------------
// Scratch
// ---------------------------------------------------------------------------
__device__ __align__(256) __half g_xs   [SEQ * DIM];
__device__ __align__(256) __half g_os   [SEQ * QDIM];
__device__ __align__(256) __half g_wqkvs[QKVDIM * DIM];
__device__ __align__(256) __half g_wos  [DIM * QDIM];

__device__ __align__(256) __half g_qh[SEQ * QDIM], g_ql[SEQ * QDIM];
__device__ __align__(256) __half g_kh[SEQ * KVDIM];
__device__ __align__(256) __half g_vh[SEQ * KVDIM];

// ---------------------------------------------------------------------------
// helpers
// ---------------------------------------------------------------------------
__device__ __forceinline__ uint32_t smem_u32(const void* p) {
    return (uint32_t)__cvta_generic_to_shared(p);
}
__device__ __forceinline__ void cp_async16(uint32_t dst, const void* src) {
    asm volatile("cp.async.cg.shared.global [%0], [%1], 16;\n" :: "r"(dst), "l"(src));
}
__device__ __forceinline__ void mma16816(float* c, const uint32_t* a, const uint32_t* b) {
    asm volatile(
        "mma.sync.aligned.m16n8k16.row.col.f32.f16.f16.f32 "
        "{%0,%1,%2,%3}, {%4,%5,%6,%7}, {%8,%9}, {%0,%1,%2,%3};\n"
        : "+f"(c[0]), "+f"(c[1]), "+f"(c[2]), "+f"(c[3])
        : "r"(a[0]), "r"(a[1]), "r"(a[2]), "r"(a[3]), "r"(b[0]), "r"(b[1]));
}
__device__ __forceinline__ void ldsm4(uint32_t* r, uint32_t addr) {
    asm volatile("ldmatrix.sync.aligned.m8n8.x4.shared.b16 {%0,%1,%2,%3}, [%4];\n"
        : "=r"(r[0]), "=r"(r[1]), "=r"(r[2]), "=r"(r[3]) : "r"(addr));
}
__device__ __forceinline__ void ldsm4t(uint32_t* r, uint32_t addr) {
    asm volatile("ldmatrix.sync.aligned.m8n8.x4.trans.shared.b16 {%0,%1,%2,%3}, [%4];\n"
        : "=r"(r[0]), "=r"(r[1]), "=r"(r[2]), "=r"(r[3]) : "r"(addr));
}
__device__ __forceinline__ uint32_t pack2h(float p0, float p1) {
    __half h0 = __float2half_rn(p0), h1 = __float2half_rn(p1);
    return ((uint32_t)*(uint16_t*)&h1 << 16) | (uint32_t)*(uint16_t*)&h0;
}
__device__ __forceinline__ void split_pack(float p0, float p1, uint32_t& hi, uint32_t& lo) {
    __half h0 = __float2half_rn(p0), h1 = __float2half_rn(p1);
    hi = ((uint32_t)*(uint16_t*)&h1 << 16) | (uint32_t)*(uint16_t*)&h0;
    __half l0 = __float2half_rn(p0 - __half2float(h0));
    __half l1 = __float2half_rn(p1 - __half2float(h1));
    lo = ((uint32_t)*(uint16_t*)&l1 << 16) | (uint32_t)*(uint16_t*)&l0;
}

// ---------------------------------------------------------------------------
// Merged fp32 -> fp16 conversion: one kernel, 16 elems/thread (R12 version)
// ---------------------------------------------------------------------------
#define U_X    ((SEQ * DIM) / 16)
#define U_WQ   ((QDIM * DIM) / 16)
#define U_WK   ((KVDIM * DIM) / 16)
#define U_WQKV (U_WQ + 2 * U_WK)
#define U_WO   ((DIM * QDIM) / 16)
#define U_TOT  (U_X + U_WQKV + U_WO)

__global__ void cvt_all(const float* __restrict__ x,
                        const float* __restrict__ wq,
                        const float* __restrict__ wk,
                        const float* __restrict__ wv,
                        const float* __restrict__ wo,
                        __half* __restrict__ xs,
                        __half* __restrict__ wqkvs,
                        __half* __restrict__ wos)
{
    size_t u = (size_t)blockIdx.x * blockDim.x + threadIdx.x;
    if (u >= U_TOT) return;
    const float* s;
    __half* d;
    if (u < U_X) {
        s = x + u * 16; d = xs + u * 16;
    } else if (u < U_X + U_WQKV) {
        size_t v = u - U_X;
        d = wqkvs + v * 16;
        if (v < U_WQ)             s = wq + v * 16;
        else if (v < U_WQ + U_WK) s = wk + (v - U_WQ) * 16;
        else                      s = wv + (v - U_WQ - U_WK) * 16;
    } else {
        size_t v = u - U_X - U_WQKV;
        s = wo + v * 16; d = wos + v * 16;
    }
    float4 a0 = *(const float4*)(s);
    float4 a1 = *(const float4*)(s + 4);
    float4 a2 = *(const float4*)(s + 8);
    float4 a3 = *(const float4*)(s + 12);
    uint4 o0, o1;
    o0.x = pack2h(a0.x, a0.y); o0.y = pack2h(a0.z, a0.w);
    o0.z = pack2h(a1.x, a1.y); o0.w = pack2h(a1.z, a1.w);
    o1.x = pack2h(a2.x, a2.y); o1.y = pack2h(a2.z, a2.w);
    o1.z = pack2h(a3.x, a3.y); o1.w = pack2h(a3.z, a3.w);
    *(uint4*)(d)     = o0;
    *(uint4*)(d + 8) = o1;
}

// ---------------------------------------------------------------------------
// fp16 NT GEMM: 128x128 block tile, BK=64, 3-stage cp.async ring (exact R12).
// 8 warps (2Mx4N), warp tile 64x32, 2 CTAs/SM.
// EPI=0: plain fp32 C. EPI=1: fused rope/scale/split epilogue.
// ---------------------------------------------------------------------------
#define BM 128
#define BN 128
#define BK 64
#define KP 72
#define NST 3
#define STG_H ((BM + BN) * KP)
#define GEMM_SMEM (NST * STG_H * 2)      // 110592 bytes

template <int EPI>
__global__ __launch_bounds__(256, 2) void gemm_fp16_nt(
    const __half* __restrict__ A, const __half* __restrict__ B,
    float* __restrict__ C,
    __half* __restrict__ Qh, __half* __restrict__ Ql,
    __half* __restrict__ Kh, __half* __restrict__ Vh,
    const float* __restrict__ cosb, const float* __restrict__ sinb,
    int M, int N, int K)
{
    extern __shared__ __half smg[];

    const int tid  = threadIdx.x;
    const int lane = tid & 31;
    const int w    = tid >> 5;
    const int bm   = blockIdx.y * BM;
    const int bn   = blockIdx.x * BN;
    const int warp_m = (w & 1) * 64;
    const int warp_n = (w >> 1) * 32;

    float acc[4][4][4];
#pragma unroll
    for (int i = 0; i < 4; i++)
#pragma unroll
        for (int j = 0; j < 4; j++)
#pragma unroll
            for (int r = 0; r < 4; r++) acc[i][j][r] = 0.0f;

    const int KB = K / BK;

    auto load_stage = [&](int kb) {
        __half* As = smg + (kb % NST) * STG_H;
        __half* Bs = As + BM * KP;
        int k0 = kb * BK;
#pragma unroll
        for (int i = 0; i < 4; i++) {
            int id  = tid + i * 256;
            int row = id >> 3;
            int c8  = (id & 7) * 8;
            cp_async16(smem_u32(As + row * KP + c8),
                       A + (size_t)(bm + row) * K + k0 + c8);
        }
#pragma unroll
        for (int i = 0; i < 4; i++) {
            int id  = tid + i * 256;
            int row = id >> 3;
            int c8  = (id & 7) * 8;
            cp_async16(smem_u32(Bs + row * KP + c8),
                       B + (size_t)(bn + row) * K + k0 + c8);
        }
        asm volatile("cp.async.commit_group;\n");
    };

    load_stage(0);
    load_stage(1);

    for (int kb = 0; kb < KB; kb++) {
        asm volatile("cp.async.wait_group 1;\n");
        __syncthreads();
        if (kb + 2 < KB) {
            load_stage(kb + 2);
        } else {
            asm volatile("cp.async.commit_group;\n");
        }

        __half* As = smg + (kb % NST) * STG_H;
        __half* Bs = As + BM * KP;

#pragma unroll
        for (int ks = 0; ks < 4; ks++) {
            uint32_t a_frag[4][4];
#pragma unroll
            for (int mt = 0; mt < 4; mt++) {
                uint32_t addr = smem_u32(
                    As + (warp_m + mt * 16 + (lane & 15)) * KP
                       + ks * 16 + (lane >> 4) * 8);
                ldsm4(a_frag[mt], addr);
            }
            uint32_t b_frag[4][2];
#pragma unroll
            for (int half = 0; half < 2; half++) {
                int nt0 = half * 2;
                int row = warp_n + nt0 * 8 + ((lane >> 4) & 1) * 8 + (lane & 7);
                int col = ks * 16 + ((lane >> 3) & 1) * 8;
                uint32_t r4[4];
                ldsm4(r4, smem_u32(Bs + row * KP + col));
                b_frag[nt0][0] = r4[0]; b_frag[nt0][1] = r4[1];
                b_frag[nt0 + 1][0] = r4[2]; b_frag[nt0 + 1][1] = r4[3];
            }
#pragma unroll
            for (int mt = 0; mt < 4; mt++)
#pragma unroll
                for (int nt = 0; nt < 4; nt++)
                    mma16816(acc[mt][nt], a_frag[mt], b_frag[nt]);
        }
    }

    const int g   = lane >> 2;
    const int tig = lane & 3;

    if (EPI == 0) {
#pragma unroll
        for (int mt = 0; mt < 4; mt++) {
#pragma unroll
            for (int nt = 0; nt < 4; nt++) {
                float* c0 = C + (size_t)(bm + warp_m + mt * 16 + g) * N
                              + bn + warp_n + nt * 8 + tig * 2;
                float* c1 = c0 + 8 * (size_t)N;
                *(float2*)c0 = make_float2(acc[mt][nt][0], acc[mt][nt][1]);
                *(float2*)c1 = make_float2(acc[mt][nt][2], acc[mt][nt][3]);
            }
        }
    } else {
        const int region = (bn < QDIM) ? 0 : ((bn < QDIM + KVDIM) ? 1 : 2);
#pragma unroll
        for (int mt = 0; mt < 4; mt++) {
            int row0 = bm + warp_m + mt * 16 + g;
            int row1 = row0 + 8;
#pragma unroll
            for (int nt = 0; nt < 4; nt++) {
                int n0 = bn + warp_n + nt * 8 + tig * 2;
                float a00 = acc[mt][nt][0], a01 = acc[mt][nt][1];
                float a10 = acc[mt][nt][2], a11 = acc[mt][nt][3];
                if (region == 2) {
                    int col = n0 - (QDIM + KVDIM);
                    *(uint32_t*)(Vh + (size_t)row0 * KVDIM + col) = pack2h(a00, a01);
                    *(uint32_t*)(Vh + (size_t)row1 * KVDIM + col) = pack2h(a10, a11);
                } else {
                    int col = (region == 0) ? n0 : (n0 - QDIM);
                    int p = (col & (HD - 1)) >> 1;
                    float c0 = cosb[row0 * (HD / 2) + p], s0 = sinb[row0 * (HD / 2) + p];
                    float c1 = cosb[row1 * (HD / 2) + p], s1 = sinb[row1 * (HD / 2) + p];
                    float r00 = a00 * c0 - a01 * s0, r01 = a00 * s0 + a01 * c0;
                    float r10 = a10 * c1 - a11 * s1, r11 = a10 * s1 + a11 * c1;
                    if (region == 0) {
                        r00 *= ATT_SCALE; r01 *= ATT_SCALE;
                        r10 *= ATT_SCALE; r11 *= ATT_SCALE;
                        uint32_t hi, lo;
                        split_pack(r00, r01, hi, lo);
                        *(uint32_t*)(Qh + (size_t)row0 * QDIM + col) = hi;
                        *(uint32_t*)(Ql + (size_t)row0 * QDIM + col) = lo;
                        split_pack(r10, r11, hi, lo);
                        *(uint32_t*)(Qh + (size_t)row1 * QDIM + col) = hi;
                        *(uint32_t*)(Ql + (size_t)row1 * QDIM + col) = lo;
                    } else {
                        *(uint32_t*)(Kh + (size_t)row0 * KVDIM + col) = pack2h(r00, r01);
                        *(uint32_t*)(Kh + (size_t)row1 * KVDIM + col) = pack2h(r10, r11);
                    }
                }
            }
        }
    }
}

// ---------------------------------------------------------------------------
// Flash attention, fp16: S = (Qh+Ql)*Kh^T, O += Ph*Vh, fp16 output.
// Single KV buffer -> 104,448 B smem -> 2 CTAs/SM (inter-CTA load/compute
// overlap replaces the double buffer; halves the wave count).
// ---------------------------------------------------------------------------
#define PDD 136
#define ATT_SMEM ((2 * 128 * PDD + 2 * 64 * PDD) * 2)   // 104448 bytes

__global__ __launch_bounds__(256, 2) void attn_mma_kernel(
    const __half* __restrict__ Qh, const __half* __restrict__ Ql,
    const __half* __restrict__ Kh, const __half* __restrict__ Vh,
    __half* __restrict__ OS)
{
    extern __shared__ __half sm[];
    __half* sQh = sm;
    __half* sQl = sQh + 128 * PDD;
    __half* bKh = sQl + 128 * PDD;      // single KV buffer
    __half* bVh = bKh + 64 * PDD;

    const int tid  = threadIdx.x;
    const int lane = tid & 31;
    const int w    = tid >> 5;
    const int q0   = blockIdx.x * 64;
    const int kvh  = blockIdx.y >> 1;
    const int h0   = kvh * 4 + (blockIdx.y & 1) * 2;

    const int warp_row = w * 16;
    const int s_row0 = q0 + (warp_row & 63) + (lane >> 2);
    const int s_row1 = s_row0 + 8;
    const int h_out  = h0 + (warp_row >> 6);

#pragma unroll
    for (int i = 0; i < 8; i++) {
        int id = tid + i * 256;
        int r = id >> 4, c8 = (id & 15) * 8;
        int s = q0 + (r & 63), h = h0 + (r >> 6);
        size_t g = ((size_t)s * NH + h) * HD + c8;
        cp_async16(smem_u32(sQh + r * PDD + c8), Qh + g);
        cp_async16(smem_u32(sQl + r * PDD + c8), Ql + g);
    }
    asm volatile("cp.async.commit_group;\n");

    float m0 = -1e30f, m1 = -1e30f, l0 = 0.f, l1 = 0.f;
    float o_acc[16][4];
#pragma unroll
    for (int i = 0; i < 16; i++)
#pragma unroll
        for (int r = 0; r < 4; r++) o_acc[i][r] = 0.f;

    int jlo = q0 - (WINDOW - 1); if (jlo < 0) jlo = 0;
    const int t0 = jlo >> 6, t1 = (q0 + 63) >> 6;

    auto load_kv = [&](int kt) {
        int kt0 = kt << 6;
#pragma unroll
        for (int i = 0; i < 4; i++) {
            int id = tid + i * 256;
            int r = id >> 4, c8 = (id & 15) * 8;
            size_t g = ((size_t)(kt0 + r) * NKV + kvh) * HD + c8;
            cp_async16(smem_u32(bKh + r * PDD + c8), Kh + g);
            cp_async16(smem_u32(bVh + r * PDD + c8), Vh + g);
        }
        asm volatile("cp.async.commit_group;\n");
    };

    load_kv(t0);

    for (int kt = t0; kt <= t1; kt++) {
        const int kt0 = kt << 6;
        asm volatile("cp.async.wait_group 0;\n");
        __syncthreads();

        float S[8][4];
#pragma unroll
        for (int nt = 0; nt < 8; nt++)
#pragma unroll
            for (int r = 0; r < 4; r++) S[nt][r] = 0.f;

#pragma unroll
        for (int ks = 0; ks < 8; ks++) {
            uint32_t a_hi[4], a_lo[4];
            uint32_t a_off = (warp_row + (lane & 15)) * PDD
                           + ks * 16 + (lane >> 4) * 8;
            ldsm4(a_hi, smem_u32(sQh + a_off));
            ldsm4(a_lo, smem_u32(sQl + a_off));
#pragma unroll
            for (int n2 = 0; n2 < 4; n2++) {
                int row = n2 * 16 + ((lane >> 4) & 1) * 8 + (lane & 7);
                int col = ks * 16 + ((lane >> 3) & 1) * 8;
                uint32_t b4[4];
                ldsm4(b4, smem_u32(bKh + row * PDD + col));
                mma16816(S[n2 * 2],     a_hi, b4);
                mma16816(S[n2 * 2 + 1], a_hi, b4 + 2);
                mma16816(S[n2 * 2],     a_lo, b4);
                mma16816(S[n2 * 2 + 1], a_lo, b4 + 2);
            }
        }

        bool edge = (kt0 + 63 > q0) || (kt0 < q0 + 63 - (WINDOW - 1));
        if (edge) {
#pragma unroll
            for (int nt = 0; nt < 8; nt++) {
                int jc = kt0 + nt * 8 + (lane & 3) * 2;
#pragma unroll
                for (int e = 0; e < 4; e++) {
                    int j = jc + (e & 1);
                    int s = (e < 2) ? s_row0 : s_row1;
                    if (!((j <= s) && (s - j < WINDOW))) S[nt][e] = -1e30f;
                }
            }
        }

        float mx0 = -1e30f, mx1 = -1e30f;
#pragma unroll
        for (int nt = 0; nt < 8; nt++) {
            mx0 = fmaxf(mx0, fmaxf(S[nt][0], S[nt][1]));
            mx1 = fmaxf(mx1, fmaxf(S[nt][2], S[nt][3]));
        }
#pragma unroll
        for (int off = 1; off <= 2; off <<= 1) {
            mx0 = fmaxf(mx0, __shfl_xor_sync(0xffffffffu, mx0, off));
            mx1 = fmaxf(mx1, __shfl_xor_sync(0xffffffffu, mx1, off));
        }
        float mn0 = fmaxf(m0, mx0), mn1 = fmaxf(m1, mx1);
        float al0 = __expf(m0 - mn0), al1 = __expf(m1 - mn1);
        m0 = mn0; m1 = mn1;

        float sum0 = 0.f, sum1 = 0.f;
        uint32_t phi[4][4];
#pragma unroll
        for (int j2 = 0; j2 < 4; j2++) {
            float p00 = __expf(S[2 * j2][0] - mn0);
            float p01 = __expf(S[2 * j2][1] - mn0);
            float p02 = __expf(S[2 * j2][2] - mn1);
            float p03 = __expf(S[2 * j2][3] - mn1);
            float p10 = __expf(S[2 * j2 + 1][0] - mn0);
            float p11 = __expf(S[2 * j2 + 1][1] - mn0);
            float p12 = __expf(S[2 * j2 + 1][2] - mn1);
            float p13 = __expf(S[2 * j2 + 1][3] - mn1);
            sum0 += p00 + p01 + p10 + p11;
            sum1 += p02 + p03 + p12 + p13;
            phi[j2][0] = pack2h(p00, p01);
            phi[j2][1] = pack2h(p02, p03);
            phi[j2][2] = pack2h(p10, p11);
            phi[j2][3] = pack2h(p12, p13);
        }
#pragma unroll
        for (int off = 1; off <= 2; off <<= 1) {
            sum0 += __shfl_xor_sync(0xffffffffu, sum0, off);
            sum1 += __shfl_xor_sync(0xffffffffu, sum1, off);
        }
        l0 = l0 * al0 + sum0;
        l1 = l1 * al1 + sum1;

#pragma unroll
        for (int i = 0; i < 16; i++) {
            o_acc[i][0] *= al0; o_acc[i][1] *= al0;
            o_acc[i][2] *= al1; o_acc[i][3] *= al1;
        }

#pragma unroll
        for (int j2 = 0; j2 < 4; j2++) {
            int row = j2 * 16 + ((lane >> 3) & 1) * 8 + (lane & 7);
#pragma unroll
            for (int d2 = 0; d2 < 8; d2++) {
                int col = d2 * 16 + ((lane >> 4) & 1) * 8;
                uint32_t bh[4];
                ldsm4t(bh, smem_u32(bVh + row * PDD + col));
                mma16816(o_acc[d2 * 2],     phi[j2], bh);
                mma16816(o_acc[d2 * 2 + 1], phi[j2], bh + 2);
            }
        }

        __syncthreads();                 // all warps done reading KV buffer
        if (kt + 1 <= t1) load_kv(kt + 1);
    }

    float inv0 = 1.0f / l0, inv1 = 1.0f / l1;
#pragma unroll
    for (int d2 = 0; d2 < 16; d2++) {
        int d = d2 * 8 + (lane & 3) * 2;
        *(uint32_t*)(OS + (size_t)s_row0 * QDIM + h_out * HD + d) =
            pack2h(o_acc[d2][0] * inv0, o_acc[d2][1] * inv0);
        *(uint32_t*)(OS + (size_t)s_row1 * QDIM + h_out * HD + d) =
            pack2h(o_acc[d2][2] * inv1, o_acc[d2][3] * inv1);
    }
}

// ---------------------------------------------------------------------------
// Launch
// ---------------------------------------------------------------------------
extern "C" void kernel_launch(void* const* d_in, const int* in_sizes, int n_in,
                              void* d_out, int out_size)
{
    const float* x    = (const float*)d_in[0];
    const float* wq   = (const float*)d_in[1];
    const float* wk   = (const float*)d_in[2];
    const float* wv   = (const float*)d_in[3];
    const float* wo   = (const float*)d_in[4];
    const float* cosb = (const float*)d_in[5];
    const float* sinb = (const float*)d_in[6];
    float* out = (float*)d_out;

    __half *xs, *os, *wqkvs, *wos, *qh, *ql, *kh, *vh;
    cudaGetSymbolAddress((void**)&xs, g_xs);
    cudaGetSymbolAddress((void**)&os, g_os);
    cudaGetSymbolAddress((void**)&wqkvs, g_wqkvs);
    cudaGetSymbolAddress((void**)&wos, g_wos);
    cudaGetSymbolAddress((void**)&qh, g_qh);
    cudaGetSymbolAddress((void**)&ql, g_ql);
    cudaGetSymbolAddress((void**)&kh, g_kh);
    cudaGetSymbolAddress((void**)&vh, g_vh);

    cudaFuncSetAttribute(gemm_fp16_nt<0>,
                         cudaFuncAttributeMaxDynamicSharedMemorySize, GEMM_SMEM);
    cudaFuncSetAttribute(gemm_fp16_nt<1>,
                         cudaFuncAttributeMaxDynamicSharedMemorySize, GEMM_SMEM);
    cudaFuncSetAttribute(attn_mma_kernel,
                         cudaFuncAttributeMaxDynamicSharedMemorySize, ATT_SMEM);

    // single merged conversion launch
    cvt_all<<<(U_TOT + 255) / 256, 256>>>(x, wq, wk, wv, wo, xs, wqkvs, wos);

    // fused QKV projection + rope + scale + split epilogue
    {
        dim3 g(QKVDIM / BN, SEQ / BM);
        gemm_fp16_nt<1><<<g, 256, GEMM_SMEM>>>(
            xs, wqkvs, nullptr, qh, ql, kh, vh, cosb, sinb, SEQ, QKVDIM, DIM);
    }

    // flash attention (2 CTAs/SM)
    {
        dim3 ga(SEQ / 64, NKV * 2);
        attn_mma_kernel<<<ga, 256, ATT_SMEM>>>(qh, ql, kh, vh, os);
    }

    // output projection
    {
        dim3 g(DIM / BN, SEQ / BM);
        gemm_fp16_nt<0><<<g, 256, GEMM_SMEM>>>(
            os, wos, out, nullptr, nullptr, nullptr, nullptr, nullptr, nullptr,
            SEQ, DIM, QDIM);
    }
}

// round 16
// speedup vs baseline: 1.0515x; 1.0266x over previous
#include <cuda_runtime.h>
#include <cuda_fp16.h>
#include <math.h>
#include <stdint.h>

#define SEQ     2048
#define DIM     4096
#define NH      32
#define NKV     8
#define HD      128
#define WINDOW  1024
#define QDIM    (NH * HD)            // 4096
#define KVDIM   (NKV * HD)           // 1024
#define QKVDIM  (QDIM + 2 * KVDIM)   // 6144
#define ATT_SCALE 0.08838834764831845f

// ---------------------------------------------------------------------------
// Scratch
// ---------------------------------------------------------------------------
__device__ __align__(256) __half g_xs   [SEQ * DIM];
__device__ __align__(256) __half g_os   [SEQ * QDIM];
__device__ __align__(256) __half g_wqkvs[QKVDIM * DIM];
__device__ __align__(256) __half g_wos  [DIM * QDIM];

__device__ __align__(256) __half g_qh[SEQ * QDIM], g_ql[SEQ * QDIM];
__device__ __align__(256) __half g_kh[SEQ * KVDIM];
__device__ __align__(256) __half g_vh[SEQ * KVDIM];

// ---------------------------------------------------------------------------
// helpers
// ---------------------------------------------------------------------------
__device__ __forceinline__ uint32_t smem_u32(const void* p) {
    return (uint32_t)__cvta_generic_to_shared(p);
}
__device__ __forceinline__ void cp_async16(uint32_t dst, const void* src) {
    asm volatile("cp.async.cg.shared.global [%0], [%1], 16;\n" :: "r"(dst), "l"(src));
}
__device__ __forceinline__ void mma16816(float* c, const uint32_t* a, const uint32_t* b) {
    asm volatile(
        "mma.sync.aligned.m16n8k16.row.col.f32.f16.f16.f32 "
        "{%0,%1,%2,%3}, {%4,%5,%6,%7}, {%8,%9}, {%0,%1,%2,%3};\n"
        : "+f"(c[0]), "+f"(c[1]), "+f"(c[2]), "+f"(c[3])
        : "r"(a[0]), "r"(a[1]), "r"(a[2]), "r"(a[3]), "r"(b[0]), "r"(b[1]));
}
__device__ __forceinline__ void ldsm4(uint32_t* r, uint32_t addr) {
    asm volatile("ldmatrix.sync.aligned.m8n8.x4.shared.b16 {%0,%1,%2,%3}, [%4];\n"
        : "=r"(r[0]), "=r"(r[1]), "=r"(r[2]), "=r"(r[3]) : "r"(addr));
}
__device__ __forceinline__ void ldsm4t(uint32_t* r, uint32_t addr) {
    asm volatile("ldmatrix.sync.aligned.m8n8.x4.trans.shared.b16 {%0,%1,%2,%3}, [%4];\n"
        : "=r"(r[0]), "=r"(r[1]), "=r"(r[2]), "=r"(r[3]) : "r"(addr));
}
__device__ __forceinline__ uint32_t pack2h(float p0, float p1) {
    __half h0 = __float2half_rn(p0), h1 = __float2half_rn(p1);
    return ((uint32_t)*(uint16_t*)&h1 << 16) | (uint32_t)*(uint16_t*)&h0;
}
__device__ __forceinline__ void split_pack(float p0, float p1, uint32_t& hi, uint32_t& lo) {
    __half h0 = __float2half_rn(p0), h1 = __float2half_rn(p1);
    hi = ((uint32_t)*(uint16_t*)&h1 << 16) | (uint32_t)*(uint16_t*)&h0;
    __half l0 = __float2half_rn(p0 - __half2float(h0));
    __half l1 = __float2half_rn(p1 - __half2float(h1));
    lo = ((uint32_t)*(uint16_t*)&l1 << 16) | (uint32_t)*(uint16_t*)&l0;
}

// ---------------------------------------------------------------------------
// Merged fp32 -> fp16 conversion: one kernel, 16 elems/thread (R12 version)
// ---------------------------------------------------------------------------
#define U_X    ((SEQ * DIM) / 16)
#define U_WQ   ((QDIM * DIM) / 16)
#define U_WK   ((KVDIM * DIM) / 16)
#define U_WQKV (U_WQ + 2 * U_WK)
#define U_WO   ((DIM * QDIM) / 16)
#define U_TOT  (U_X + U_WQKV + U_WO)

__global__ void cvt_all(const float* __restrict__ x,
                        const float* __restrict__ wq,
                        const float* __restrict__ wk,
                        const float* __restrict__ wv,
                        const float* __restrict__ wo,
                        __half* __restrict__ xs,
                        __half* __restrict__ wqkvs,
                        __half* __restrict__ wos)
{
    size_t u = (size_t)blockIdx.x * blockDim.x + threadIdx.x;
    if (u >= U_TOT) return;
    const float* s;
    __half* d;
    if (u < U_X) {
        s = x + u * 16; d = xs + u * 16;
    } else if (u < U_X + U_WQKV) {
        size_t v = u - U_X;
        d = wqkvs + v * 16;
        if (v < U_WQ)             s = wq + v * 16;
        else if (v < U_WQ + U_WK) s = wk + (v - U_WQ) * 16;
        else                      s = wv + (v - U_WQ - U_WK) * 16;
    } else {
        size_t v = u - U_X - U_WQKV;
        s = wo + v * 16; d = wos + v * 16;
    }
    float4 a0 = *(const float4*)(s);
    float4 a1 = *(const float4*)(s + 4);
    float4 a2 = *(const float4*)(s + 8);
    float4 a3 = *(const float4*)(s + 12);
    uint4 o0, o1;
    o0.x = pack2h(a0.x, a0.y); o0.y = pack2h(a0.z, a0.w);
    o0.z = pack2h(a1.x, a1.y); o0.w = pack2h(a1.z, a1.w);
    o1.x = pack2h(a2.x, a2.y); o1.y = pack2h(a2.z, a2.w);
    o1.z = pack2h(a3.x, a3.y); o1.w = pack2h(a3.z, a3.w);
    *(uint4*)(d)     = o0;
    *(uint4*)(d + 8) = o1;
}

// ---------------------------------------------------------------------------
// fp16 NT GEMM: 128x128 block tile, BK=64, 3-stage cp.async ring (exact R12).
// 8 warps (2Mx4N), warp tile 64x32, 2 CTAs/SM.
// EPI=0: plain fp32 C. EPI=1: fused rope/scale/split epilogue.
// ---------------------------------------------------------------------------
#define BM 128
#define BN 128
#define BK 64
#define KP 72
#define NST 3
#define STG_H ((BM + BN) * KP)
#define GEMM_SMEM (NST * STG_H * 2)      // 110592 bytes

template <int EPI>
__global__ __launch_bounds__(256, 2) void gemm_fp16_nt(
    const __half* __restrict__ A, const __half* __restrict__ B,
    float* __restrict__ C,
    __half* __restrict__ Qh, __half* __restrict__ Ql,
    __half* __restrict__ Kh, __half* __restrict__ Vh,
    const float* __restrict__ cosb, const float* __restrict__ sinb,
    int M, int N, int K)
{
    extern __shared__ __half smg[];

    const int tid  = threadIdx.x;
    const int lane = tid & 31;
    const int w    = tid >> 5;
    const int bm   = blockIdx.y * BM;
    const int bn   = blockIdx.x * BN;
    const int warp_m = (w & 1) * 64;
    const int warp_n = (w >> 1) * 32;

    float acc[4][4][4];
#pragma unroll
    for (int i = 0; i < 4; i++)
#pragma unroll
        for (int j = 0; j < 4; j++)
#pragma unroll
            for (int r = 0; r < 4; r++) acc[i][j][r] = 0.0f;

    const int KB = K / BK;

    auto load_stage = [&](int kb) {
        __half* As = smg + (kb % NST) * STG_H;
        __half* Bs = As + BM * KP;
        int k0 = kb * BK;
#pragma unroll
        for (int i = 0; i < 4; i++) {
            int id  = tid + i * 256;
            int row = id >> 3;
            int c8  = (id & 7) * 8;
            cp_async16(smem_u32(As + row * KP + c8),
                       A + (size_t)(bm + row) * K + k0 + c8);
        }
#pragma unroll
        for (int i = 0; i < 4; i++) {
            int id  = tid + i * 256;
            int row = id >> 3;
            int c8  = (id & 7) * 8;
            cp_async16(smem_u32(Bs + row * KP + c8),
                       B + (size_t)(bn + row) * K + k0 + c8);
        }
        asm volatile("cp.async.commit_group;\n");
    };

    load_stage(0);
    load_stage(1);

    for (int kb = 0; kb < KB; kb++) {
        asm volatile("cp.async.wait_group 1;\n");
        __syncthreads();
        if (kb + 2 < KB) {
            load_stage(kb + 2);
        } else {
            asm volatile("cp.async.commit_group;\n");
        }

        __half* As = smg + (kb % NST) * STG_H;
        __half* Bs = As + BM * KP;

#pragma unroll
        for (int ks = 0; ks < 4; ks++) {
            uint32_t a_frag[4][4];
#pragma unroll
            for (int mt = 0; mt < 4; mt++) {
                uint32_t addr = smem_u32(
                    As + (warp_m + mt * 16 + (lane & 15)) * KP
                       + ks * 16 + (lane >> 4) * 8);
                ldsm4(a_frag[mt], addr);
            }
            uint32_t b_frag[4][2];
#pragma unroll
            for (int half = 0; half < 2; half++) {
                int nt0 = half * 2;
                int row = warp_n + nt0 * 8 + ((lane >> 4) & 1) * 8 + (lane & 7);
                int col = ks * 16 + ((lane >> 3) & 1) * 8;
                uint32_t r4[4];
                ldsm4(r4, smem_u32(Bs + row * KP + col));
                b_frag[nt0][0] = r4[0]; b_frag[nt0][1] = r4[1];
                b_frag[nt0 + 1][0] = r4[2]; b_frag[nt0 + 1][1] = r4[3];
            }
#pragma unroll
            for (int mt = 0; mt < 4; mt++)
#pragma unroll
                for (int nt = 0; nt < 4; nt++)
                    mma16816(acc[mt][nt], a_frag[mt], b_frag[nt]);
        }
    }

    const int g   = lane >> 2;
    const int tig = lane & 3;

    if (EPI == 0) {
#pragma unroll
        for (int mt = 0; mt < 4; mt++) {
#pragma unroll
            for (int nt = 0; nt < 4; nt++) {
                float* c0 = C + (size_t)(bm + warp_m + mt * 16 + g) * N
                              + bn + warp_n + nt * 8 + tig * 2;
                float* c1 = c0 + 8 * (size_t)N;
                *(float2*)c0 = make_float2(acc[mt][nt][0], acc[mt][nt][1]);
                *(float2*)c1 = make_float2(acc[mt][nt][2], acc[mt][nt][3]);
            }
        }
    } else {
        const int region = (bn < QDIM) ? 0 : ((bn < QDIM + KVDIM) ? 1 : 2);
#pragma unroll
        for (int mt = 0; mt < 4; mt++) {
            int row0 = bm + warp_m + mt * 16 + g;
            int row1 = row0 + 8;
#pragma unroll
            for (int nt = 0; nt < 4; nt++) {
                int n0 = bn + warp_n + nt * 8 + tig * 2;
                float a00 = acc[mt][nt][0], a01 = acc[mt][nt][1];
                float a10 = acc[mt][nt][2], a11 = acc[mt][nt][3];
                if (region == 2) {
                    int col = n0 - (QDIM + KVDIM);
                    *(uint32_t*)(Vh + (size_t)row0 * KVDIM + col) = pack2h(a00, a01);
                    *(uint32_t*)(Vh + (size_t)row1 * KVDIM + col) = pack2h(a10, a11);
                } else {
                    int col = (region == 0) ? n0 : (n0 - QDIM);
                    int p = (col & (HD - 1)) >> 1;
                    float c0 = cosb[row0 * (HD / 2) + p], s0 = sinb[row0 * (HD / 2) + p];
                    float c1 = cosb[row1 * (HD / 2) + p], s1 = sinb[row1 * (HD / 2) + p];
                    float r00 = a00 * c0 - a01 * s0, r01 = a00 * s0 + a01 * c0;
                    float r10 = a10 * c1 - a11 * s1, r11 = a10 * s1 + a11 * c1;
                    if (region == 0) {
                        r00 *= ATT_SCALE; r01 *= ATT_SCALE;
                        r10 *= ATT_SCALE; r11 *= ATT_SCALE;
                        uint32_t hi, lo;
                        split_pack(r00, r01, hi, lo);
                        *(uint32_t*)(Qh + (size_t)row0 * QDIM + col) = hi;
                        *(uint32_t*)(Ql + (size_t)row0 * QDIM + col) = lo;
                        split_pack(r10, r11, hi, lo);
                        *(uint32_t*)(Qh + (size_t)row1 * QDIM + col) = hi;
                        *(uint32_t*)(Ql + (size_t)row1 * QDIM + col) = lo;
                    } else {
                        *(uint32_t*)(Kh + (size_t)row0 * KVDIM + col) = pack2h(r00, r01);
                        *(uint32_t*)(Kh + (size_t)row1 * KVDIM + col) = pack2h(r10, r11);
                    }
                }
            }
        }
    }
}

// ---------------------------------------------------------------------------
// Flash attention, fp16: S = (Qh+Ql)*Kh^T, O += Ph*Vh, fp16 output.
// R12 double-buffered KV structure; Q fragments hoisted into registers
// (loop-invariant -> removes 16 ldsm.x4 per key tile per warp);
// l-reduction deferred to the end (linearity of rescale).
// ---------------------------------------------------------------------------
#define PDD 136
#define ATT_SMEM ((2 * 128 * PDD + 2 * 2 * 64 * PDD) * 2)

__global__ __launch_bounds__(256, 1) void attn_mma_kernel(
    const __half* __restrict__ Qh, const __half* __restrict__ Ql,
    const __half* __restrict__ Kh, const __half* __restrict__ Vh,
    __half* __restrict__ OS)
{
    extern __shared__ __half sm[];
    __half* sQh = sm;
    __half* sQl = sQh + 128 * PDD;
    __half* sKV = sQl + 128 * PDD;

    const int tid  = threadIdx.x;
    const int lane = tid & 31;
    const int w    = tid >> 5;
    const int q0   = blockIdx.x * 64;
    const int kvh  = blockIdx.y >> 1;
    const int h0   = kvh * 4 + (blockIdx.y & 1) * 2;

    const int warp_row = w * 16;
    const int s_row0 = q0 + (warp_row & 63) + (lane >> 2);
    const int s_row1 = s_row0 + 8;
    const int h_out  = h0 + (warp_row >> 6);

#pragma unroll
    for (int i = 0; i < 8; i++) {
        int id = tid + i * 256;
        int r = id >> 4, c8 = (id & 15) * 8;
        int s = q0 + (r & 63), h = h0 + (r >> 6);
        size_t g = ((size_t)s * NH + h) * HD + c8;
        cp_async16(smem_u32(sQh + r * PDD + c8), Qh + g);
        cp_async16(smem_u32(sQl + r * PDD + c8), Ql + g);
    }
    asm volatile("cp.async.commit_group;\n");

    float m0 = -1e30f, m1 = -1e30f, l0 = 0.f, l1 = 0.f;
    float o_acc[16][4];
#pragma unroll
    for (int i = 0; i < 16; i++)
#pragma unroll
        for (int r = 0; r < 4; r++) o_acc[i][r] = 0.f;

    int jlo = q0 - (WINDOW - 1); if (jlo < 0) jlo = 0;
    const int t0 = jlo >> 6, t1 = (q0 + 63) >> 6;

    auto load_kv = [&](int kt, int buf) {
        __half* b = sKV + buf * 2 * 64 * PDD;
        int kt0 = kt << 6;
#pragma unroll
        for (int i = 0; i < 4; i++) {
            int id = tid + i * 256;
            int r = id >> 4, c8 = (id & 15) * 8;
            size_t g = ((size_t)(kt0 + r) * NKV + kvh) * HD + c8;
            cp_async16(smem_u32(b + r * PDD + c8), Kh + g);
            cp_async16(smem_u32(b + 64 * PDD + r * PDD + c8), Vh + g);
        }
        asm volatile("cp.async.commit_group;\n");
    };

    load_kv(t0, 0);

    // ---- hoist Q fragments into registers (loop-invariant) ----
    uint32_t qf_hi[8][4], qf_lo[8][4];
    {
        asm volatile("cp.async.wait_group 1;\n");   // Q group (oldest) done
        __syncthreads();
#pragma unroll
        for (int ks = 0; ks < 8; ks++) {
            uint32_t a_off = (warp_row + (lane & 15)) * PDD
                           + ks * 16 + (lane >> 4) * 8;
            ldsm4(qf_hi[ks], smem_u32(sQh + a_off));
            ldsm4(qf_lo[ks], smem_u32(sQl + a_off));
        }
    }

    for (int kt = t0; kt <= t1; kt++) {
        const int buf = (kt - t0) & 1;
        const int kt0 = kt << 6;
        if (kt + 1 <= t1) {
            load_kv(kt + 1, buf ^ 1);
            asm volatile("cp.async.wait_group 1;\n");
        } else {
            asm volatile("cp.async.wait_group 0;\n");
        }
        __syncthreads();

        __half* bKh = sKV + buf * 2 * 64 * PDD;
        __half* bVh = bKh + 64 * PDD;

        float S[8][4];
#pragma unroll
        for (int nt = 0; nt < 8; nt++)
#pragma unroll
            for (int r = 0; r < 4; r++) S[nt][r] = 0.f;

#pragma unroll
        for (int ks = 0; ks < 8; ks++) {
#pragma unroll
            for (int n2 = 0; n2 < 4; n2++) {
                int row = n2 * 16 + ((lane >> 4) & 1) * 8 + (lane & 7);
                int col = ks * 16 + ((lane >> 3) & 1) * 8;
                uint32_t b4[4];
                ldsm4(b4, smem_u32(bKh + row * PDD + col));
                mma16816(S[n2 * 2],     qf_hi[ks], b4);
                mma16816(S[n2 * 2 + 1], qf_hi[ks], b4 + 2);
                mma16816(S[n2 * 2],     qf_lo[ks], b4);
                mma16816(S[n2 * 2 + 1], qf_lo[ks], b4 + 2);
            }
        }

        bool edge = (kt0 + 63 > q0) || (kt0 < q0 + 63 - (WINDOW - 1));
        if (edge) {
#pragma unroll
            for (int nt = 0; nt < 8; nt++) {
                int jc = kt0 + nt * 8 + (lane & 3) * 2;
#pragma unroll
                for (int e = 0; e < 4; e++) {
                    int j = jc + (e & 1);
                    int s = (e < 2) ? s_row0 : s_row1;
                    if (!((j <= s) && (s - j < WINDOW))) S[nt][e] = -1e30f;
                }
            }
        }

        float mx0 = -1e30f, mx1 = -1e30f;
#pragma unroll
        for (int nt = 0; nt < 8; nt++) {
            mx0 = fmaxf(mx0, fmaxf(S[nt][0], S[nt][1]));
            mx1 = fmaxf(mx1, fmaxf(S[nt][2], S[nt][3]));
        }
#pragma unroll
        for (int off = 1; off <= 2; off <<= 1) {
            mx0 = fmaxf(mx0, __shfl_xor_sync(0xffffffffu, mx0, off));
            mx1 = fmaxf(mx1, __shfl_xor_sync(0xffffffffu, mx1, off));
        }
        float mn0 = fmaxf(m0, mx0), mn1 = fmaxf(m1, mx1);
        float al0 = __expf(m0 - mn0), al1 = __expf(m1 - mn1);
        m0 = mn0; m1 = mn1;

        float sum0 = 0.f, sum1 = 0.f;
        uint32_t phi[4][4];
#pragma unroll
        for (int j2 = 0; j2 < 4; j2++) {
            float p00 = __expf(S[2 * j2][0] - mn0);
            float p01 = __expf(S[2 * j2][1] - mn0);
            float p02 = __expf(S[2 * j2][2] - mn1);
            float p03 = __expf(S[2 * j2][3] - mn1);
            float p10 = __expf(S[2 * j2 + 1][0] - mn0);
            float p11 = __expf(S[2 * j2 + 1][1] - mn0);
            float p12 = __expf(S[2 * j2 + 1][2] - mn1);
            float p13 = __expf(S[2 * j2 + 1][3] - mn1);
            sum0 += p00 + p01 + p10 + p11;
            sum1 += p02 + p03 + p12 + p13;
            phi[j2][0] = pack2h(p00, p01);
            phi[j2][1] = pack2h(p02, p03);
            phi[j2][2] = pack2h(p10, p11);
            phi[j2][3] = pack2h(p12, p13);
        }
        // deferred: per-lane partial l (reduced once after the loop)
        l0 = l0 * al0 + sum0;
        l1 = l1 * al1 + sum1;

#pragma unroll
        for (int i = 0; i < 16; i++) {
            o_acc[i][0] *= al0; o_acc[i][1] *= al0;
            o_acc[i][2] *= al1; o_acc[i][3] *= al1;
        }

#pragma unroll
        for (int j2 = 0; j2 < 4; j2++) {
            int row = j2 * 16 + ((lane >> 3) & 1) * 8 + (lane & 7);
#pragma unroll
            for (int d2 = 0; d2 < 8; d2++) {
                int col = d2 * 16 + ((lane >> 4) & 1) * 8;
                uint32_t bh[4];
                ldsm4t(bh, smem_u32(bVh + row * PDD + col));
                mma16816(o_acc[d2 * 2],     phi[j2], bh);
                mma16816(o_acc[d2 * 2 + 1], phi[j2], bh + 2);
            }
        }
        __syncthreads();
    }

    // final l reduction (was per-tile in R12; deferred by linearity)
#pragma unroll
    for (int off = 1; off <= 2; off <<= 1) {
        l0 += __shfl_xor_sync(0xffffffffu, l0, off);
        l1 += __shfl_xor_sync(0xffffffffu, l1, off);
    }

    float inv0 = 1.0f / l0, inv1 = 1.0f / l1;
#pragma unroll
    for (int d2 = 0; d2 < 16; d2++) {
        int d = d2 * 8 + (lane & 3) * 2;
        *(uint32_t*)(OS + (size_t)s_row0 * QDIM + h_out * HD + d) =
            pack2h(o_acc[d2][0] * inv0, o_acc[d2][1] * inv0);
        *(uint32_t*)(OS + (size_t)s_row1 * QDIM + h_out * HD + d) =
            pack2h(o_acc[d2][2] * inv1, o_acc[d2][3] * inv1);
    }
}

// ---------------------------------------------------------------------------
// Launch
// ---------------------------------------------------------------------------
extern "C" void kernel_launch(void* const* d_in, const int* in_sizes, int n_in,
                              void* d_out, int out_size)
{
    const float* x    = (const float*)d_in[0];
    const float* wq   = (const float*)d_in[1];
    const float* wk   = (const float*)d_in[2];
    const float* wv   = (const float*)d_in[3];
    const float* wo   = (const float*)d_in[4];
    const float* cosb = (const float*)d_in[5];
    const float* sinb = (const float*)d_in[6];
    float* out = (float*)d_out;

    __half *xs, *os, *wqkvs, *wos, *qh, *ql, *kh, *vh;
    cudaGetSymbolAddress((void**)&xs, g_xs);
    cudaGetSymbolAddress((void**)&os, g_os);
    cudaGetSymbolAddress((void**)&wqkvs, g_wqkvs);
    cudaGetSymbolAddress((void**)&wos, g_wos);
    cudaGetSymbolAddress((void**)&qh, g_qh);
    cudaGetSymbolAddress((void**)&ql, g_ql);
    cudaGetSymbolAddress((void**)&kh, g_kh);
    cudaGetSymbolAddress((void**)&vh, g_vh);

    cudaFuncSetAttribute(gemm_fp16_nt<0>,
                         cudaFuncAttributeMaxDynamicSharedMemorySize, GEMM_SMEM);
    cudaFuncSetAttribute(gemm_fp16_nt<1>,
                         cudaFuncAttributeMaxDynamicSharedMemorySize, GEMM_SMEM);
    cudaFuncSetAttribute(attn_mma_kernel,
                         cudaFuncAttributeMaxDynamicSharedMemorySize, ATT_SMEM);

    // single merged conversion launch
    cvt_all<<<(U_TOT + 255) / 256, 256>>>(x, wq, wk, wv, wo, xs, wqkvs, wos);

    // fused QKV projection + rope + scale + split epilogue
    {
        dim3 g(QKVDIM / BN, SEQ / BM);
        gemm_fp16_nt<1><<<g, 256, GEMM_SMEM>>>(
            xs, wqkvs, nullptr, qh, ql, kh, vh, cosb, sinb, SEQ, QKVDIM, DIM);
    }

    // flash attention
    {
        dim3 ga(SEQ / 64, NKV * 2);
        attn_mma_kernel<<<ga, 256, ATT_SMEM>>>(qh, ql, kh, vh, os);
    }

    // output projection
    {
        dim3 g(DIM / BN, SEQ / BM);
        gemm_fp16_nt<0><<<g, 256, GEMM_SMEM>>>(
            os, wos, out, nullptr, nullptr, nullptr, nullptr, nullptr, nullptr,
            SEQ, DIM, QDIM);
    }
}